// round 12
// baseline (speedup 1.0000x reference)
#include <cuda_runtime.h>
#include <cstdint>

// Problem constants
#define BB 64      // batch
#define SS 256     // seq length
#define VV 2048    // ntokens
#define HH 512     // nhid
#define GROWS 16   // gathered rows per CTA (32KB smem tile)
#define GSPLIT (SS / GROWS)   // 16 splits per batch

// Scratch (no allocations). Zero-initialized at module load.
// g_h1pre's ==0 invariant is restored by k_gemm2 each call.
__device__ float g_h1pre[BB * HH];          // gather accumulator (pre bias/relu)
__device__ float g_h2part[8][BB][HH];       // GEMM1 K-split partials (no atomics)

// ---------------------------------------------------------------------------
// K1: TMA bulk-copy gather.  grid = (64 batches, 16 splits of 16 positions),
// block = 128 threads.  One cp.async.bulk (UBLKCP) per 2KB W1 row -> zero
// register pressure, full MLP from the TMA engine.  Rows land in smem; each
// thread reduces its float4 column across 16 rows and atomicAdds into h1pre.
// y==0 slice also seeds out = b3.  Index dtype (int64/int32) runtime-detected.
// ---------------------------------------------------------------------------
__global__ void __launch_bounds__(128) k_gather(
        const int* __restrict__ x32,
        const float* __restrict__ W1,
        const float* __restrict__ b3,
        float* __restrict__ out) {
    __shared__ __align__(128) float tile[GROWS][HH];       // 32 KB
    __shared__ __align__(8) unsigned long long mbar;
    __shared__ unsigned rowidx[GROWS];
    __shared__ int s_is64;

    const int t = threadIdx.x;
    const int b = blockIdx.x;

    // Seed out = b3 (out is poisoned before timing).
    if (blockIdx.y == 0) {
        const int gid = b * 128 + t;          // 0..8191
        out[gid]        = b3[gid & (SS - 1)];
        out[gid + 8192] = b3[gid & (SS - 1)];
    }

    // Index dtype detection: int64 -> odd 32-bit words of first 128 elems are 0.
    if (t == 0) s_is64 = 1;
    __syncthreads();
    if (x32[2 * t + 1] != 0) s_is64 = 0;      // racy same-value store: fine
    __syncthreads();

    const int p0 = blockIdx.y * GROWS;
    if (t < GROWS) {
        unsigned tok;
        if (s_is64) tok = (unsigned)((const long long*)x32)[b * SS + p0 + t];
        else        tok = (unsigned)x32[b * SS + p0 + t];
        rowidx[t] = tok + (unsigned)(p0 + t) * VV;          // row index in W1
    }
    const unsigned mbar_a = (unsigned)__cvta_generic_to_shared(&mbar);
    if (t == 0) {
        asm volatile("mbarrier.init.shared.b64 [%0], 1;" :: "r"(mbar_a) : "memory");
    }
    __syncthreads();

    if (t == 0) {
        asm volatile("mbarrier.arrive.expect_tx.shared.b64 _, [%0], %1;"
                     :: "r"(mbar_a), "r"((unsigned)(GROWS * HH * 4)) : "memory");
        const unsigned dst0 = (unsigned)__cvta_generic_to_shared(&tile[0][0]);
        #pragma unroll
        for (int i = 0; i < GROWS; i++) {
            const float* src = W1 + (size_t)rowidx[i] * HH;
            asm volatile(
                "cp.async.bulk.shared::cluster.global.mbarrier::complete_tx::bytes"
                " [%0], [%1], %2, [%3];"
                :: "r"(dst0 + i * (HH * 4)), "l"(src),
                   "r"((unsigned)(HH * 4)), "r"(mbar_a) : "memory");
        }
    }

    // Wait for all 32KB to land (parity 0: barrier freshly init'd each launch).
    asm volatile(
        "{\n\t.reg .pred P1;\n\t"
        "WAIT_%=:\n\t"
        "mbarrier.try_wait.parity.acquire.cta.shared::cta.b64 P1, [%0], %1;\n\t"
        "@P1 bra.uni DONE_%=;\n\t"
        "bra.uni WAIT_%=;\n\t"
        "DONE_%=:\n\t}"
        :: "r"(mbar_a), "r"(0u) : "memory");

    // Reduce 16 rows: thread t owns float4 column t.
    float4 acc = *(const float4*)&tile[0][4 * t];
    #pragma unroll
    for (int r = 1; r < GROWS; r++) {
        float4 v = *(const float4*)&tile[r][4 * t];
        acc.x += v.x; acc.y += v.y; acc.z += v.z; acc.w += v.w;
    }
    float* dst = &g_h1pre[b * HH + 4 * t];
    atomicAdd(dst + 0, acc.x);
    atomicAdd(dst + 1, acc.y);
    atomicAdd(dst + 2, acc.z);
    atomicAdd(dst + 3, acc.w);
}

// ---------------------------------------------------------------------------
// K2: GEMM1 partial: g_h2part[kbs] = relu(h1pre+b1)[:, kb..] @ W2[kb.., nb..]
// grid = (16 n-tiles of 32, 8 k-splits of 64), block = 128 threads.
// Pure STG.128 epilogue -> zero atomics.  float4 staging everywhere.
// ---------------------------------------------------------------------------
__global__ void __launch_bounds__(128) k_gemm1(
        const float* __restrict__ b1,
        const float* __restrict__ W2) {
    const int nb  = blockIdx.x * 32;
    const int kbs = blockIdx.y;          // 0..7
    const int kb  = kbs * 64;
    const int t   = threadIdx.x;
    const int m4  = (t >> 3) * 4;        // 0..60
    const int n4  = (t & 7) * 4;         // 0..28

    __shared__ float As[64][33];
    __shared__ __align__(16) float Bs[32][32];

    float acc[4][4] = {};

    for (int kk = 0; kk < 64; kk += 32) {
        __syncthreads();
        #pragma unroll
        for (int i = 0; i < 4; i++) {           // As: 64x32, float4 loads
            int idx = i * 128 + t;
            int mm = idx >> 3, k4 = (idx & 7) * 4;
            int kg = kb + kk + k4;
            float4 v  = *(const float4*)&g_h1pre[mm * HH + kg];
            float4 bb = *(const float4*)&b1[kg];
            As[mm][k4 + 0] = fmaxf(v.x + bb.x, 0.f);
            As[mm][k4 + 1] = fmaxf(v.y + bb.y, 0.f);
            As[mm][k4 + 2] = fmaxf(v.z + bb.z, 0.f);
            As[mm][k4 + 3] = fmaxf(v.w + bb.w, 0.f);
        }
        #pragma unroll
        for (int i = 0; i < 2; i++) {           // Bs: 32x32, float4 loads
            int idx = i * 128 + t;
            int k = idx >> 3, nn4 = (idx & 7) * 4;
            *(float4*)&Bs[k][nn4] =
                *(const float4*)&W2[(kb + kk + k) * HH + nb + nn4];
        }
        __syncthreads();

        #pragma unroll
        for (int k = 0; k < 32; k++) {
            float4 b4 = *(const float4*)&Bs[k][n4];
            float a0 = As[m4 + 0][k];
            float a1 = As[m4 + 1][k];
            float a2 = As[m4 + 2][k];
            float a3 = As[m4 + 3][k];
            acc[0][0] += a0 * b4.x; acc[0][1] += a0 * b4.y; acc[0][2] += a0 * b4.z; acc[0][3] += a0 * b4.w;
            acc[1][0] += a1 * b4.x; acc[1][1] += a1 * b4.y; acc[1][2] += a1 * b4.z; acc[1][3] += a1 * b4.w;
            acc[2][0] += a2 * b4.x; acc[2][1] += a2 * b4.y; acc[2][2] += a2 * b4.z; acc[2][3] += a2 * b4.w;
            acc[3][0] += a3 * b4.x; acc[3][1] += a3 * b4.y; acc[3][2] += a3 * b4.z; acc[3][3] += a3 * b4.w;
        }
    }

    #pragma unroll
    for (int i = 0; i < 4; i++)                 // STG.128 epilogue, no atomics
        *(float4*)&g_h2part[kbs][m4 + i][nb + n4] =
            make_float4(acc[i][0], acc[i][1], acc[i][2], acc[i][3]);
}

// ---------------------------------------------------------------------------
// K3: GEMM2: out += relu(sum_p h2part[p] + b2)(64x512) @ W3(512x256), K-split.
// grid = (8 n-tiles of 32, 16 k-splits of 32), block = 128 threads.
// The 8-partial summation is fused into A-staging. Also resets g_h1pre
// (its last reader, K2, precedes this kernel in stream order).
// ---------------------------------------------------------------------------
__global__ void __launch_bounds__(128) k_gemm2(
        const float* __restrict__ b2,
        const float* __restrict__ W3,
        float* __restrict__ out) {
    const int nb = blockIdx.x * 32;
    const int kb = blockIdx.y * 32;
    const int t  = threadIdx.x;
    const int m4 = (t >> 3) * 4;
    const int n4 = (t & 7) * 4;

    // Reset g_h1pre: 128 CTAs x 128 threads -> 2 elems/thread.
    {
        const int base = (blockIdx.y * gridDim.x + blockIdx.x) * 128 + t;
        g_h1pre[base] = 0.0f;
        g_h1pre[base + 16384] = 0.0f;
    }

    __shared__ float As[64][33];
    __shared__ __align__(16) float Bs[32][32];

    float acc[4][4] = {};

    #pragma unroll
    for (int i = 0; i < 4; i++) {               // As = relu(sum partials + b2)
        int idx = i * 128 + t;
        int mm = idx >> 3, k4 = (idx & 7) * 4;
        int kg = kb + k4;
        float4 s = *(const float4*)&b2[kg];
        #pragma unroll
        for (int p = 0; p < 8; p++) {
            float4 v = *(const float4*)&g_h2part[p][mm][kg];
            s.x += v.x; s.y += v.y; s.z += v.z; s.w += v.w;
        }
        As[mm][k4 + 0] = fmaxf(s.x, 0.f);
        As[mm][k4 + 1] = fmaxf(s.y, 0.f);
        As[mm][k4 + 2] = fmaxf(s.z, 0.f);
        As[mm][k4 + 3] = fmaxf(s.w, 0.f);
    }
    #pragma unroll
    for (int i = 0; i < 2; i++) {               // Bs: 32x32 of W3
        int idx = i * 128 + t;
        int k = idx >> 3, nn4 = (idx & 7) * 4;
        *(float4*)&Bs[k][nn4] =
            *(const float4*)&W3[(kb + k) * SS + nb + nn4];
    }
    __syncthreads();

    #pragma unroll
    for (int k = 0; k < 32; k++) {
        float4 b4 = *(const float4*)&Bs[k][n4];
        float a0 = As[m4 + 0][k];
        float a1 = As[m4 + 1][k];
        float a2 = As[m4 + 2][k];
        float a3 = As[m4 + 3][k];
        acc[0][0] += a0 * b4.x; acc[0][1] += a0 * b4.y; acc[0][2] += a0 * b4.z; acc[0][3] += a0 * b4.w;
        acc[1][0] += a1 * b4.x; acc[1][1] += a1 * b4.y; acc[1][2] += a1 * b4.z; acc[1][3] += a1 * b4.w;
        acc[2][0] += a2 * b4.x; acc[2][1] += a2 * b4.y; acc[2][2] += a2 * b4.z; acc[2][3] += a2 * b4.w;
        acc[3][0] += a3 * b4.x; acc[3][1] += a3 * b4.y; acc[3][2] += a3 * b4.z; acc[3][3] += a3 * b4.w;
    }

    #pragma unroll
    for (int i = 0; i < 4; i++)
        #pragma unroll
        for (int j = 0; j < 4; j++)
            atomicAdd(&out[(m4 + i) * SS + nb + n4 + j], acc[i][j]);
}

// ---------------------------------------------------------------------------
extern "C" void kernel_launch(void* const* d_in, const int* in_sizes, int n_in,
                              void* d_out, int out_size) {
    const int*   x  = (const int*)d_in[0];   // int32 or int64, detected on device
    const float* W1 = (const float*)d_in[1];
    const float* b1 = (const float*)d_in[2];
    const float* W2 = (const float*)d_in[3];
    const float* b2 = (const float*)d_in[4];
    const float* W3 = (const float*)d_in[5];
    const float* b3 = (const float*)d_in[6];
    float* out = (float*)d_out;

    k_gather<<<dim3(BB, GSPLIT), 128>>>(x, W1, b3, out);
    k_gemm1<<<dim3(16, 8), 128>>>(b1, W2);
    k_gemm2<<<dim3(8, 16), 128>>>(b2, W3, out);
}

// round 13
// speedup vs baseline: 1.1364x; 1.1364x over previous
#include <cuda_runtime.h>

// Problem constants
#define BB 64      // batch
#define SS 256     // seq length
#define VV 2048    // ntokens
#define HH 512     // nhid
#define NSPLIT 8   // sequence splits for the gather
#define SP (SS / NSPLIT)   // positions per gather CTA = 32
#define MCTA 128   // CTAs in fused MLP kernel (single wave: 128 < 148 SMs)

// Scratch (no allocations). Zero-initialized at module load.
// g_h1pre's ==0 invariant is restored by k_mlp phase B each call.
__device__ float g_h1pre[BB * HH];          // gather accumulator (pre bias/relu)
__device__ float g_h2part[8][BB][HH];       // GEMM1 K-split partials (no atomics)
__device__ unsigned g_bar;                  // monotonic generation barrier

// ---------------------------------------------------------------------------
// K1: gather partial-sum -> atomicAdd into g_h1pre.   (R4/R11 config, proven
// to sit at the ~2.85 TB/s pattern ceiling.)
// grid = (256, 8): x = 64 batches x 4 H-chunks, y = 8 seq-splits of 32.
// block = 128 threads (one h column each). y==0 slice also seeds out = b3.
// Handles both int64 and int32 index layouts (runtime-detected).
// ---------------------------------------------------------------------------
__global__ void k_gather(const int* __restrict__ x32,
                         const float* __restrict__ W1,
                         const float* __restrict__ b3,
                         float* __restrict__ out) {
    const int t = threadIdx.x;

    if (blockIdx.y == 0) {
        const int gid = blockIdx.x * 128 + t;        // 0..32767
        if (gid < BB * SS) out[gid] = b3[gid & (SS - 1)];
    }

    __shared__ int s_is64;
    if (t == 0) s_is64 = 1;
    __syncthreads();
    if (x32[2 * t + 1] != 0) s_is64 = 0;   // racy same-value store: fine
    __syncthreads();
    const int is64 = s_is64;

    const int b  = blockIdx.x >> 2;                   // batch
    const int h  = ((blockIdx.x & 3) << 7) | t;       // 0..511
    const int p0 = blockIdx.y * SP;                   // first position

    __shared__ unsigned rb[SP];
    if (t < SP) {
        unsigned tok;
        if (is64) tok = (unsigned)((const long long*)x32)[b * SS + p0 + t];
        else      tok = (unsigned)x32[b * SS + p0 + t];
        rb[t] = (tok + (unsigned)(p0 + t) * VV) << 9;   // * HH
    }
    __syncthreads();

    float a0 = 0.f, a1 = 0.f, a2 = 0.f, a3 = 0.f;
    #pragma unroll
    for (int p = 0; p < SP; p += 4) {
        a0 += W1[rb[p + 0] + h];
        a1 += W1[rb[p + 1] + h];
        a2 += W1[rb[p + 2] + h];
        a3 += W1[rb[p + 3] + h];
    }
    atomicAdd(&g_h1pre[b * HH + h], (a0 + a1) + (a2 + a3));
}

// ---------------------------------------------------------------------------
// K2: fused MLP.  128 CTAs x 128 threads, single wave => grid barrier safe.
// Phase A (GEMM1): g_h2part[kbs] = relu(h1pre+b1)[:, kb..] @ W2[kb.., nb..]
//                  (pure STG.128 epilogue, no atomics)
// Phase B (GEMM2): out += relu(sum_p h2part + b2) @ W3, K-split, atomics.
//                  Also resets g_h1pre to zero for the next call/replay.
// ---------------------------------------------------------------------------
__global__ void __launch_bounds__(128) k_mlp(
        const float* __restrict__ b1,
        const float* __restrict__ W2,
        const float* __restrict__ b2,
        const float* __restrict__ W3,
        float* __restrict__ out) {
    const int t   = threadIdx.x;
    const int cta = blockIdx.x;
    const int m4  = (t >> 3) * 4;    // 0..60
    const int n4  = (t & 7) * 4;     // 0..28

    __shared__ float As[64][33];
    __shared__ __align__(16) float Bs[32][32];

    // ---- Phase A: GEMM1 partial (nb = 32-col tile, kb = 64-wide K-split) --
    {
        const int nb  = (cta & 15) * 32;
        const int kbs = cta >> 4;            // 0..7
        const int kb  = kbs * 64;
        float acc[4][4] = {};

        for (int kk = 0; kk < 64; kk += 32) {
            __syncthreads();
            #pragma unroll
            for (int i = 0; i < 4; i++) {           // As: 64x32, float4 loads
                int idx = i * 128 + t;
                int mm = idx >> 3, k4 = (idx & 7) * 4;
                int kg = kb + kk + k4;
                float4 v  = *(const float4*)&g_h1pre[mm * HH + kg];
                float4 bb = *(const float4*)&b1[kg];
                As[mm][k4 + 0] = fmaxf(v.x + bb.x, 0.f);
                As[mm][k4 + 1] = fmaxf(v.y + bb.y, 0.f);
                As[mm][k4 + 2] = fmaxf(v.z + bb.z, 0.f);
                As[mm][k4 + 3] = fmaxf(v.w + bb.w, 0.f);
            }
            #pragma unroll
            for (int i = 0; i < 2; i++) {           // Bs: 32x32, float4 loads
                int idx = i * 128 + t;
                int k = idx >> 3, nn4 = (idx & 7) * 4;
                *(float4*)&Bs[k][nn4] =
                    *(const float4*)&W2[(kb + kk + k) * HH + nb + nn4];
            }
            __syncthreads();

            #pragma unroll
            for (int k = 0; k < 32; k++) {
                float4 b4 = *(const float4*)&Bs[k][n4];
                float a0 = As[m4 + 0][k];
                float a1 = As[m4 + 1][k];
                float a2 = As[m4 + 2][k];
                float a3 = As[m4 + 3][k];
                acc[0][0] += a0 * b4.x; acc[0][1] += a0 * b4.y; acc[0][2] += a0 * b4.z; acc[0][3] += a0 * b4.w;
                acc[1][0] += a1 * b4.x; acc[1][1] += a1 * b4.y; acc[1][2] += a1 * b4.z; acc[1][3] += a1 * b4.w;
                acc[2][0] += a2 * b4.x; acc[2][1] += a2 * b4.y; acc[2][2] += a2 * b4.z; acc[2][3] += a2 * b4.w;
                acc[3][0] += a3 * b4.x; acc[3][1] += a3 * b4.y; acc[3][2] += a3 * b4.z; acc[3][3] += a3 * b4.w;
            }
        }
        #pragma unroll
        for (int i = 0; i < 4; i++)                 // STG.128, no atomics
            *(float4*)&g_h2part[kbs][m4 + i][nb + n4] =
                make_float4(acc[i][0], acc[i][1], acc[i][2], acc[i][3]);
    }

    // ---- Grid barrier (128 CTAs, generation-counting, replay-safe) ------
    __syncthreads();
    if (t == 0) {
        __threadfence();
        unsigned v = atomicAdd(&g_bar, 1u);
        unsigned tgt = (v / MCTA + 1u) * MCTA;
        unsigned cur;
        do {
            asm volatile("ld.acquire.gpu.global.u32 %0, [%1];"
                         : "=r"(cur) : "l"(&g_bar) : "memory");
            if (cur < tgt) __nanosleep(32);
        } while (cur < tgt);
        __threadfence();
    }
    __syncthreads();

    // ---- Phase B: reset h1pre + GEMM2 -----------------------------------
    {   // g_h1pre reset (last reader was Phase A staging): 2 elems/thread.
        const int base = cta * 128 + t;              // 0..16383
        g_h1pre[base] = 0.0f;
        g_h1pre[base + 16384] = 0.0f;
    }
    {
        const int nb = (cta & 7) * 32;
        const int kb = (cta >> 3) * 32;              // 16 k-splits of 32
        float acc[4][4] = {};

        __syncthreads();
        #pragma unroll
        for (int i = 0; i < 4; i++) {               // As = relu(sum partials + b2)
            int idx = i * 128 + t;
            int mm = idx >> 3, k4 = (idx & 7) * 4;
            int kg = kb + k4;
            float4 s = *(const float4*)&b2[kg];
            #pragma unroll
            for (int p = 0; p < 8; p++) {
                float4 v = *(const float4*)&g_h2part[p][mm][kg];
                s.x += v.x; s.y += v.y; s.z += v.z; s.w += v.w;
            }
            As[mm][k4 + 0] = fmaxf(s.x, 0.f);
            As[mm][k4 + 1] = fmaxf(s.y, 0.f);
            As[mm][k4 + 2] = fmaxf(s.z, 0.f);
            As[mm][k4 + 3] = fmaxf(s.w, 0.f);
        }
        #pragma unroll
        for (int i = 0; i < 2; i++) {               // Bs: 32x32 of W3
            int idx = i * 128 + t;
            int k = idx >> 3, nn4 = (idx & 7) * 4;
            *(float4*)&Bs[k][nn4] =
                *(const float4*)&W3[(kb + k) * SS + nb + nn4];
        }
        __syncthreads();

        #pragma unroll
        for (int k = 0; k < 32; k++) {
            float4 b4 = *(const float4*)&Bs[k][n4];
            float a0 = As[m4 + 0][k];
            float a1 = As[m4 + 1][k];
            float a2 = As[m4 + 2][k];
            float a3 = As[m4 + 3][k];
            acc[0][0] += a0 * b4.x; acc[0][1] += a0 * b4.y; acc[0][2] += a0 * b4.z; acc[0][3] += a0 * b4.w;
            acc[1][0] += a1 * b4.x; acc[1][1] += a1 * b4.y; acc[1][2] += a1 * b4.z; acc[1][3] += a1 * b4.w;
            acc[2][0] += a2 * b4.x; acc[2][1] += a2 * b4.y; acc[2][2] += a2 * b4.z; acc[2][3] += a2 * b4.w;
            acc[3][0] += a3 * b4.x; acc[3][1] += a3 * b4.y; acc[3][2] += a3 * b4.z; acc[3][3] += a3 * b4.w;
        }

        #pragma unroll
        for (int i = 0; i < 4; i++)
            #pragma unroll
            for (int j = 0; j < 4; j++)
                atomicAdd(&out[(m4 + i) * SS + nb + n4 + j], acc[i][j]);
    }
}

// ---------------------------------------------------------------------------
extern "C" void kernel_launch(void* const* d_in, const int* in_sizes, int n_in,
                              void* d_out, int out_size) {
    const int*   x  = (const int*)d_in[0];   // int32 or int64, detected on device
    const float* W1 = (const float*)d_in[1];
    const float* b1 = (const float*)d_in[2];
    const float* W2 = (const float*)d_in[3];
    const float* b2 = (const float*)d_in[4];
    const float* W3 = (const float*)d_in[5];
    const float* b3 = (const float*)d_in[6];
    float* out = (float*)d_out;

    k_gather<<<dim3(256, NSPLIT), 128>>>(x, W1, b3, out);
    k_mlp<<<MCTA, 128>>>(b1, W2, b2, W3, out);
}